// round 1
// baseline (speedup 1.0000x reference)
#include <cuda_runtime.h>
#include <cuda_bf16.h>
#include <cstdint>
#include <cstddef>

// Problem constants
#define SEQ    512
#define BATCH  64
#define UNITS  512
#define GATES  2048          // 4*UNITS, Keras order i,f,g,o
#define NCTA   128           // persistent grid (<=148 SMs -> co-resident)

// -------------------- device scratch (no cudaMalloc allowed) --------------------
__device__ float g_xpre[(size_t)BATCH * SEQ * GATES];   // [b][t][gate_col], 256 MB
__device__ float g_h[2][UNITS * BATCH];                 // h transposed [u][b], double buffered
__device__ unsigned g_arrive;                           // zero-initialized, monotonic
__device__ unsigned g_release;

// -------------------- helpers --------------------
__device__ __forceinline__ float sigmoid_f(float x) {
    return 1.0f / (1.0f + __expf(-x));
}
__device__ __forceinline__ float tanh_f(float x) {
    float e = __expf(-2.0f * fabsf(x));
    float t = (1.0f - e) / (1.0f + e);
    return copysignf(t, x);
}

// Monotonic sense-free grid barrier: ticket/round scheme survives multiple
// kernel launches (graph replays) without any reset.
__device__ __forceinline__ void grid_barrier() {
    __syncthreads();
    if (threadIdx.x == 0) {
        __threadfence();
        unsigned ticket = atomicAdd(&g_arrive, 1u);
        unsigned round  = ticket >> 7;                    // / NCTA (=128)
        if ((ticket & (NCTA - 1u)) == (NCTA - 1u)) {
            atomicAdd(&g_release, 1u);
        } else {
            while ((int)(*(volatile unsigned*)&g_release - (round + 1u)) < 0) { }
        }
        __threadfence();
    }
    __syncthreads();
}

// -------------------- kernel 1: Xpre = x @ Wx + bias --------------------
// M=32768 (b*512+t), K=512, N=2048.  Classic 128x128 tile, 8x8 per thread.
__global__ __launch_bounds__(256, 2) void xpre_gemm(
    const float* __restrict__ X,     // [32768, 512] (x viewed row-major)
    const float* __restrict__ Wx,    // [512, 2048]
    const float* __restrict__ bias)  // [2048]
{
    __shared__ float As[8][128];
    __shared__ float Bs[8][128];

    const int tid = threadIdx.x;
    const int bm = blockIdx.y << 7;
    const int bn = blockIdx.x << 7;
    const int ty = tid >> 4, tx = tid & 15;

    const int a_m = tid >> 1;
    const int a_k = (tid & 1) << 2;
    const int b_k = tid >> 5;
    const int b_n = (tid & 31) << 2;

    float acc[8][8];
#pragma unroll
    for (int i = 0; i < 8; i++)
#pragma unroll
        for (int j = 0; j < 8; j++) acc[i][j] = 0.0f;

    const float* Aptr = X + (size_t)(bm + a_m) * 512 + a_k;
    const float* Bptr = Wx + (size_t)b_k * 2048 + bn + b_n;

    for (int k0 = 0; k0 < 512; k0 += 8) {
        float4 av = *(const float4*)(Aptr + k0);
        float4 bv = *(const float4*)(Bptr + (size_t)k0 * 2048);
        __syncthreads();
        As[a_k + 0][a_m] = av.x;
        As[a_k + 1][a_m] = av.y;
        As[a_k + 2][a_m] = av.z;
        As[a_k + 3][a_m] = av.w;
        *(float4*)&Bs[b_k][b_n] = bv;
        __syncthreads();
#pragma unroll
        for (int kk = 0; kk < 8; kk++) {
            float ar[8], br[8];
            *(float4*)&ar[0] = *(const float4*)&As[kk][ty * 8];
            *(float4*)&ar[4] = *(const float4*)&As[kk][ty * 8 + 4];
            *(float4*)&br[0] = *(const float4*)&Bs[kk][tx * 8];
            *(float4*)&br[4] = *(const float4*)&Bs[kk][tx * 8 + 4];
#pragma unroll
            for (int i = 0; i < 8; i++)
#pragma unroll
                for (int j = 0; j < 8; j++)
                    acc[i][j] = fmaf(ar[i], br[j], acc[i][j]);
        }
    }

    float brow[8];
#pragma unroll
    for (int j = 0; j < 8; j++) brow[j] = bias[bn + tx * 8 + j];

#pragma unroll
    for (int i = 0; i < 8; i++) {
        size_t row = (size_t)(bm + ty * 8 + i) * 2048 + bn + tx * 8;
        float4 lo = make_float4(acc[i][0] + brow[0], acc[i][1] + brow[1],
                                acc[i][2] + brow[2], acc[i][3] + brow[3]);
        float4 hi = make_float4(acc[i][4] + brow[4], acc[i][5] + brow[5],
                                acc[i][6] + brow[6], acc[i][7] + brow[7]);
        *(float4*)&g_xpre[row]     = lo;
        *(float4*)&g_xpre[row + 4] = hi;
    }
}

// -------------------- kernel 2: persistent LSTM recurrence --------------------
// Grid 128 = 32 unit-groups (16 units each) x 4 batch-groups (16 batches each).
// Per step per CTA: z[16b x 64col] = Xpre tile + sH[512 x 16b]^T-GEMM with
// smem-resident Wh slice [512 x 64col]. Thread mapping: 16 K-slices x (8c x 2b),
// 8x8 register tile, smem tree-reduction over K-slices.
//
// smem layout (floats): sWh[32768] | sPart[16*1028=16448] (sH[512*16] aliases
// its first 32KB during the GEMM phase) | sZ[1024]
#define SMEM_FLOATS (32768 + 16448 + 1024)
#define SMEM_BYTES  (SMEM_FLOATS * 4)

__global__ __launch_bounds__(256, 1) void lstm_seq(
    const float* __restrict__ h0,   // [64, 512]
    const float* __restrict__ c0,   // [64, 512]
    const float* __restrict__ Wh,   // [512, 2048]
    float* __restrict__ out)        // [512, 64, 512]
{
    extern __shared__ float smem[];
    float* sWh   = smem;                 // 32768
    float* sPart = smem + 32768;         // 16448 (rows of 1028: 1024 + pad)
    float* sZ    = sPart + 16448;        // 1024

    const int tid = threadIdx.x;
    const int cg = blockIdx.x & 31;      // unit group
    const int bg = blockIdx.x >> 5;      // batch group
    const int u0 = cg << 4;
    const int b0 = bg << 4;

    // ---- load Wh slice into smem: sWh[k][g*16+j] = Wh[k][g*512 + u0 + j]
    {
        const float4* W4 = (const float4*)Wh;
        float4* sW4 = (float4*)sWh;
        const int u0q = u0 >> 2;
        for (int i = tid; i < 8192; i += 256) {
            int k = i >> 4;
            int gate = (i >> 2) & 3;
            int q = i & 3;
            sW4[i] = W4[(size_t)k * 512 + gate * 128 + u0q + q];
        }
    }

    // ---- init g_h[0] from h0 (transpose to [u][b]); cooperative across grid
    for (int i = (blockIdx.x << 8) + tid; i < UNITS * BATCH; i += NCTA * 256) {
        int u = i >> 6, b = i & 63;
        g_h[0][i] = h0[b * 512 + u];
    }

    // ---- per-thread cell state (one (b,u) per thread, persists in a register)
    const int ul = tid & 15, bl = tid >> 4;
    float c_reg = c0[(b0 + bl) * 512 + u0 + ul];

    // ---- GEMM thread mapping
    const int ks = tid >> 4;             // K slice 0..15 (32 k's each)
    const int c8 = (tid >> 1) & 7;       // col octet
    const int b8 = tid & 1;              // batch octet

    float4* sH4 = (float4*)sPart;        // sH[k][16b] aliases sPart head
    const float4* sW4c = (const float4*)sWh;

    grid_barrier();                      // g_h[0] ready everywhere

    for (int t = 0; t < SEQ; t++) {
        const int cur = t & 1;

        // prefetch this step's Xpre tile early (DRAM latency hidden by GEMM)
        float xv[4];
#pragma unroll
        for (int m = 0; m < 4; m++) {
            int o = tid + (m << 8);
            int bb = o >> 6, cc = o & 63;
            int gate = cc >> 4, j = cc & 15;
            xv[m] = g_xpre[((size_t)(b0 + bb) * 512 + t) * 2048 + gate * 512 + u0 + j];
        }

        // load h tile: sH[k][0..15] = g_h[cur][k*64 + b0 .. +16]
        {
            const float4* gh4 = (const float4*)g_h[cur];
#pragma unroll
            for (int r = 0; r < 2; r++) {
                int k = (tid << 1) + r;
                int gb = (k << 4) + (b0 >> 2);
                float4 v0 = gh4[gb], v1 = gh4[gb + 1], v2 = gh4[gb + 2], v3 = gh4[gb + 3];
                int sb = k << 2;
                sH4[sb] = v0; sH4[sb + 1] = v1; sH4[sb + 2] = v2; sH4[sb + 3] = v3;
            }
        }
        __syncthreads();

        // ---- GEMM: acc[8b][8c] over this thread's 32-k slice
        float acc[8][8];
#pragma unroll
        for (int i = 0; i < 8; i++)
#pragma unroll
            for (int j = 0; j < 8; j++) acc[i][j] = 0.0f;
        {
            const int kb = ks << 5;
#pragma unroll 4
            for (int k = kb; k < kb + 32; k++) {
                float hr[8], wr[8];
                *(float4*)&hr[0] = sH4[(k << 2) + (b8 << 1)];
                *(float4*)&hr[4] = sH4[(k << 2) + (b8 << 1) + 1];
                *(float4*)&wr[0] = sW4c[(k << 4) + (c8 << 1)];
                *(float4*)&wr[4] = sW4c[(k << 4) + (c8 << 1) + 1];
#pragma unroll
                for (int i = 0; i < 8; i++)
#pragma unroll
                    for (int j = 0; j < 8; j++)
                        acc[i][j] = fmaf(hr[i], wr[j], acc[i][j]);
            }
        }
        __syncthreads();   // everyone done reading sH before overwriting sPart

        // ---- write partials: sPart[ks][o], o = (b8*8+i)*64 + c8*8 + j
        {
            float* p = sPart + ks * 1028 + (c8 << 3);
#pragma unroll
            for (int i = 0; i < 8; i++) {
                int off = (((b8 << 3) + i) << 6);
                *(float4*)&p[off]     = make_float4(acc[i][0], acc[i][1], acc[i][2], acc[i][3]);
                *(float4*)&p[off + 4] = make_float4(acc[i][4], acc[i][5], acc[i][6], acc[i][7]);
            }
        }
        __syncthreads();

        // ---- reduce 16 K-slices + add Xpre -> sZ[o]
#pragma unroll
        for (int m = 0; m < 4; m++) {
            int o = tid + (m << 8);
            float s0 = 0.f, s1 = 0.f, s2 = 0.f, s3 = 0.f;
#pragma unroll
            for (int q = 0; q < 4; q++) {
                s0 += sPart[(q     ) * 1028 + o];
                s1 += sPart[(q +  4) * 1028 + o];
                s2 += sPart[(q +  8) * 1028 + o];
                s3 += sPart[(q + 12) * 1028 + o];
            }
            sZ[o] = ((s0 + s1) + (s2 + s3)) + xv[m];
        }
        __syncthreads();

        // ---- elementwise LSTM cell (Keras gate order i,f,g,o)
        {
            float zi = sZ[(bl << 6) + ul];
            float zf = sZ[(bl << 6) + 16 + ul];
            float zg = sZ[(bl << 6) + 32 + ul];
            float zo = sZ[(bl << 6) + 48 + ul];
            float ig = sigmoid_f(zi);
            float fg = sigmoid_f(zf);
            float gg = tanh_f(zg);
            float og = sigmoid_f(zo);
            c_reg = fg * c_reg + ig * gg;
            float hv = og * tanh_f(c_reg);
            g_h[cur ^ 1][(u0 + ul) * 64 + b0 + bl] = hv;
            out[((size_t)t * 64 + b0 + bl) * 512 + u0 + ul] = hv;
        }

        grid_barrier();    // h fully published before next step reads it
    }
}

// -------------------- launch --------------------
// Input order (metadata): x [64,512,512], h0 [64,512], c0 [64,512],
//                         Wx [512,2048], Wh [512,2048], b [2048]
extern "C" void kernel_launch(void* const* d_in, const int* in_sizes, int n_in,
                              void* d_out, int out_size) {
    const float* x    = (const float*)d_in[0];
    const float* h0   = (const float*)d_in[1];
    const float* c0   = (const float*)d_in[2];
    const float* Wx   = (const float*)d_in[3];
    const float* Wh   = (const float*)d_in[4];
    const float* bias = (const float*)d_in[5];
    float* out = (float*)d_out;

    cudaFuncSetAttribute(lstm_seq, cudaFuncAttributeMaxDynamicSharedMemorySize, SMEM_BYTES);

    xpre_gemm<<<dim3(16, 256), 256>>>(x, Wx, bias);
    lstm_seq<<<NCTA, 256, SMEM_BYTES>>>(h0, c0, Wh, out);
}

// round 3
// speedup vs baseline: 1.1916x; 1.1916x over previous
#include <cuda_runtime.h>
#include <cuda_bf16.h>
#include <cstdint>
#include <cstddef>

// Problem constants
#define SEQ    512
#define BATCH  64
#define UNITS  512
#define GATES  2048          // 4*UNITS, Keras order i,f,g,o
#define NCTA   128           // persistent grid (<=148 SMs -> co-resident)

// -------------------- device scratch (no cudaMalloc allowed) --------------------
__device__ float g_xpre[(size_t)BATCH * SEQ * GATES];   // [b][t][gate_col], 256 MB
__device__ float g_h[2][UNITS * BATCH];                 // h transposed [u][b], double buffered
__device__ unsigned g_arrive;                           // zero-initialized, monotonic
__device__ unsigned g_release;

// -------------------- helpers --------------------
__device__ __forceinline__ uint32_t f32_to_tf32(float x) {
    uint32_t r; asm("cvt.rna.tf32.f32 %0, %1;" : "=r"(r) : "f"(x)); return r;
}

__device__ __forceinline__ void mma_tf32(float c[4],
                                         uint32_t a0, uint32_t a1, uint32_t a2, uint32_t a3,
                                         uint32_t b0, uint32_t b1) {
    asm volatile(
        "mma.sync.aligned.m16n8k8.row.col.f32.tf32.tf32.f32 "
        "{%0,%1,%2,%3}, {%4,%5,%6,%7}, {%8,%9}, {%0,%1,%2,%3};"
        : "+f"(c[0]), "+f"(c[1]), "+f"(c[2]), "+f"(c[3])
        : "r"(a0), "r"(a1), "r"(a2), "r"(a3), "r"(b0), "r"(b1));
}

__device__ __forceinline__ float sigmoid_f(float x) {
    return 1.0f / (1.0f + __expf(-x));
}
__device__ __forceinline__ float tanh_f(float x) {
    float e = __expf(-2.0f * fabsf(x));
    float t = (1.0f - e) / (1.0f + e);
    return copysignf(t, x);
}

// Monotonic sense-free grid barrier (survives graph replays without reset).
__device__ __forceinline__ void grid_barrier() {
    __syncthreads();
    if (threadIdx.x == 0) {
        __threadfence();
        unsigned ticket = atomicAdd(&g_arrive, 1u);
        unsigned round  = ticket >> 7;                    // / NCTA (=128)
        if ((ticket & (NCTA - 1u)) == (NCTA - 1u)) {
            atomicAdd(&g_release, 1u);
        } else {
            while ((int)(*(volatile unsigned*)&g_release - (round + 1u)) < 0) { }
        }
        __threadfence();
    }
    __syncthreads();
}

// -------------------- kernel 1: Xpre = x @ Wx + bias (mma.sync tf32) --------------------
// M=32768 (b*512+t), K=512, N=2048.
// CTA tile 128x128, 8 warps in 4x2 grid (warp tile 32 rows x 64 cols).
// K streamed in chunks of 32. smem pitches chosen for conflict-free m16n8k8
// fragment loads: A[m][k] pitch 36 (bank = 4*gid + tig), B[k][n] pitch 136
// (bank = 8*tig + gid).
#define A_PITCH 36
#define B_PITCH 136

__global__ __launch_bounds__(256, 2) void xpre_mma(
    const float* __restrict__ X,     // [32768, 512]
    const float* __restrict__ Wx,    // [512, 2048]
    const float* __restrict__ bias)  // [2048]
{
    __shared__ uint32_t sA[128 * A_PITCH];   // 18 KB
    __shared__ uint32_t sB[32 * B_PITCH];    // 17.4 KB

    const int tid  = threadIdx.x;
    const int lane = tid & 31;
    const int wid  = tid >> 5;
    const int m0 = blockIdx.y << 7;
    const int n0 = blockIdx.x << 7;
    const int wr = wid >> 1;          // warp row 0..3 (32 rows each)
    const int wc = wid & 1;           // warp col 0..1 (64 cols each)
    const int gid = lane >> 2;        // 0..7
    const int tig = lane & 3;         // 0..3

    float acc[2][8][4];
#pragma unroll
    for (int mf = 0; mf < 2; mf++)
#pragma unroll
        for (int nf = 0; nf < 8; nf++)
#pragma unroll
            for (int q = 0; q < 4; q++) acc[mf][nf][q] = 0.0f;

    for (int kc = 0; kc < 16; kc++) {
        const int k0 = kc << 5;

        // ---- A chunk: [128 m x 32 k], coalesced float4, tf32 convert
#pragma unroll
        for (int it = 0; it < 4; it++) {
            int idx = tid + (it << 8);           // 0..1023 float4s
            int row = idx >> 3;                  // 0..127
            int c4  = (idx & 7) << 2;            // 0,4,..28
            float4 v = *(const float4*)(X + (size_t)(m0 + row) * 512 + k0 + c4);
            uint4 t;
            t.x = f32_to_tf32(v.x); t.y = f32_to_tf32(v.y);
            t.z = f32_to_tf32(v.z); t.w = f32_to_tf32(v.w);
            *(uint4*)&sA[row * A_PITCH + c4] = t;
        }

        // ---- B chunk: [32 k x 128 n], coalesced float4, tf32 convert
#pragma unroll
        for (int it = 0; it < 4; it++) {
            int idx = tid + (it << 8);           // 0..1023 float4s
            int k  = idx >> 5;                   // 0..31
            int c4 = (idx & 31) << 2;            // 0..124
            float4 v = *(const float4*)(Wx + (size_t)(k0 + k) * 2048 + n0 + c4);
            uint4 t;
            t.x = f32_to_tf32(v.x); t.y = f32_to_tf32(v.y);
            t.z = f32_to_tf32(v.z); t.w = f32_to_tf32(v.w);
            *(uint4*)&sB[k * B_PITCH + c4] = t;
        }
        __syncthreads();

        // ---- 4 k8-steps of m16n8k8
#pragma unroll
        for (int k8 = 0; k8 < 4; k8++) {
            const int kb = k8 << 3;
            uint32_t a[2][4];
#pragma unroll
            for (int mf = 0; mf < 2; mf++) {
                int r = wr * 32 + mf * 16 + gid;
                a[mf][0] = sA[r * A_PITCH + kb + tig];
                a[mf][1] = sA[(r + 8) * A_PITCH + kb + tig];
                a[mf][2] = sA[r * A_PITCH + kb + tig + 4];
                a[mf][3] = sA[(r + 8) * A_PITCH + kb + tig + 4];
            }
#pragma unroll
            for (int nf = 0; nf < 8; nf++) {
                int n = wc * 64 + nf * 8 + gid;
                uint32_t b0 = sB[(kb + tig) * B_PITCH + n];
                uint32_t b1 = sB[(kb + tig + 4) * B_PITCH + n];
                mma_tf32(acc[0][nf], a[0][0], a[0][1], a[0][2], a[0][3], b0, b1);
                mma_tf32(acc[1][nf], a[1][0], a[1][1], a[1][2], a[1][3], b0, b1);
            }
        }
        __syncthreads();
    }

    // ---- epilogue: + bias -> g_xpre
#pragma unroll
    for (int nf = 0; nf < 8; nf++) {
        int col = n0 + wc * 64 + nf * 8 + tig * 2;
        float bv0 = bias[col], bv1 = bias[col + 1];
#pragma unroll
        for (int mf = 0; mf < 2; mf++) {
            int r0 = m0 + wr * 32 + mf * 16 + gid;
            float2 lo = make_float2(acc[mf][nf][0] + bv0, acc[mf][nf][1] + bv1);
            float2 hi = make_float2(acc[mf][nf][2] + bv0, acc[mf][nf][3] + bv1);
            *(float2*)&g_xpre[(size_t)r0 * 2048 + col]       = lo;
            *(float2*)&g_xpre[(size_t)(r0 + 8) * 2048 + col] = hi;
        }
    }
}

// -------------------- kernel 2: persistent LSTM recurrence (unchanged R1) --------------------
#define SMEM_FLOATS (32768 + 16448 + 1024)
#define SMEM_BYTES  (SMEM_FLOATS * 4)

__global__ __launch_bounds__(256, 1) void lstm_seq(
    const float* __restrict__ h0,   // [64, 512]
    const float* __restrict__ c0,   // [64, 512]
    const float* __restrict__ Wh,   // [512, 2048]
    float* __restrict__ out)        // [512, 64, 512]
{
    extern __shared__ float smem[];
    float* sWh   = smem;                 // 32768
    float* sPart = smem + 32768;         // 16448 (rows of 1028: 1024 + pad)
    float* sZ    = sPart + 16448;        // 1024

    const int tid = threadIdx.x;
    const int cg = blockIdx.x & 31;      // unit group
    const int bg = blockIdx.x >> 5;      // batch group
    const int u0 = cg << 4;
    const int b0 = bg << 4;

    // ---- load Wh slice into smem: sWh[k][g*16+j] = Wh[k][g*512 + u0 + j]
    {
        const float4* W4 = (const float4*)Wh;
        float4* sW4 = (float4*)sWh;
        const int u0q = u0 >> 2;
        for (int i = tid; i < 8192; i += 256) {
            int k = i >> 4;
            int gate = (i >> 2) & 3;
            int q = i & 3;
            sW4[i] = W4[(size_t)k * 512 + gate * 128 + u0q + q];
        }
    }

    // ---- init g_h[0] from h0 (transpose to [u][b]); cooperative across grid
    for (int i = (blockIdx.x << 8) + tid; i < UNITS * BATCH; i += NCTA * 256) {
        int u = i >> 6, b = i & 63;
        g_h[0][i] = h0[b * 512 + u];
    }

    // ---- per-thread cell state
    const int ul = tid & 15, bl = tid >> 4;
    float c_reg = c0[(b0 + bl) * 512 + u0 + ul];

    // ---- GEMM thread mapping
    const int ks = tid >> 4;             // K slice 0..15 (32 k's each)
    const int c8 = (tid >> 1) & 7;       // col octet
    const int b8 = tid & 1;              // batch octet

    float4* sH4 = (float4*)sPart;        // sH[k][16b] aliases sPart head
    const float4* sW4c = (const float4*)sWh;

    grid_barrier();                      // g_h[0] ready everywhere

    for (int t = 0; t < SEQ; t++) {
        const int cur = t & 1;

        // prefetch this step's Xpre tile early
        float xv[4];
#pragma unroll
        for (int m = 0; m < 4; m++) {
            int o = tid + (m << 8);
            int bb = o >> 6, cc = o & 63;
            int gate = cc >> 4, j = cc & 15;
            xv[m] = g_xpre[((size_t)(b0 + bb) * 512 + t) * 2048 + gate * 512 + u0 + j];
        }

        // load h tile: sH[k][0..15] = g_h[cur][k*64 + b0 .. +16]
        {
            const float4* gh4 = (const float4*)g_h[cur];
#pragma unroll
            for (int r = 0; r < 2; r++) {
                int k = (tid << 1) + r;
                int gb = (k << 4) + (b0 >> 2);
                float4 v0 = gh4[gb], v1 = gh4[gb + 1], v2 = gh4[gb + 2], v3 = gh4[gb + 3];
                int sb = k << 2;
                sH4[sb] = v0; sH4[sb + 1] = v1; sH4[sb + 2] = v2; sH4[sb + 3] = v3;
            }
        }
        __syncthreads();

        // ---- GEMM: acc[8b][8c] over this thread's 32-k slice
        float acc[8][8];
#pragma unroll
        for (int i = 0; i < 8; i++)
#pragma unroll
            for (int j = 0; j < 8; j++) acc[i][j] = 0.0f;
        {
            const int kb = ks << 5;
#pragma unroll 4
            for (int k = kb; k < kb + 32; k++) {
                float hr[8], wr[8];
                *(float4*)&hr[0] = sH4[(k << 2) + (b8 << 1)];
                *(float4*)&hr[4] = sH4[(k << 2) + (b8 << 1) + 1];
                *(float4*)&wr[0] = sW4c[(k << 4) + (c8 << 1)];
                *(float4*)&wr[4] = sW4c[(k << 4) + (c8 << 1) + 1];
#pragma unroll
                for (int i = 0; i < 8; i++)
#pragma unroll
                    for (int j = 0; j < 8; j++)
                        acc[i][j] = fmaf(hr[i], wr[j], acc[i][j]);
            }
        }
        __syncthreads();

        // ---- write partials
        {
            float* p = sPart + ks * 1028 + (c8 << 3);
#pragma unroll
            for (int i = 0; i < 8; i++) {
                int off = (((b8 << 3) + i) << 6);
                *(float4*)&p[off]     = make_float4(acc[i][0], acc[i][1], acc[i][2], acc[i][3]);
                *(float4*)&p[off + 4] = make_float4(acc[i][4], acc[i][5], acc[i][6], acc[i][7]);
            }
        }
        __syncthreads();

        // ---- reduce 16 K-slices + add Xpre -> sZ[o]
#pragma unroll
        for (int m = 0; m < 4; m++) {
            int o = tid + (m << 8);
            float s0 = 0.f, s1 = 0.f, s2 = 0.f, s3 = 0.f;
#pragma unroll
            for (int q = 0; q < 4; q++) {
                s0 += sPart[(q     ) * 1028 + o];
                s1 += sPart[(q +  4) * 1028 + o];
                s2 += sPart[(q +  8) * 1028 + o];
                s3 += sPart[(q + 12) * 1028 + o];
            }
            sZ[o] = ((s0 + s1) + (s2 + s3)) + xv[m];
        }
        __syncthreads();

        // ---- elementwise LSTM cell (Keras gate order i,f,g,o)
        {
            float zi = sZ[(bl << 6) + ul];
            float zf = sZ[(bl << 6) + 16 + ul];
            float zg = sZ[(bl << 6) + 32 + ul];
            float zo = sZ[(bl << 6) + 48 + ul];
            float ig = sigmoid_f(zi);
            float fg = sigmoid_f(zf);
            float gg = tanh_f(zg);
            float og = sigmoid_f(zo);
            c_reg = fg * c_reg + ig * gg;
            float hv = og * tanh_f(c_reg);
            g_h[cur ^ 1][(u0 + ul) * 64 + b0 + bl] = hv;
            out[((size_t)t * 64 + b0 + bl) * 512 + u0 + ul] = hv;
        }

        grid_barrier();    // h fully published before next step reads it
    }
}

// -------------------- launch --------------------
// Input order (metadata): x [64,512,512], h0 [64,512], c0 [64,512],
//                         Wx [512,2048], Wh [512,2048], b [2048]
extern "C" void kernel_launch(void* const* d_in, const int* in_sizes, int n_in,
                              void* d_out, int out_size) {
    const float* x    = (const float*)d_in[0];
    const float* h0   = (const float*)d_in[1];
    const float* c0   = (const float*)d_in[2];
    const float* Wx   = (const float*)d_in[3];
    const float* Wh   = (const float*)d_in[4];
    const float* bias = (const float*)d_in[5];
    float* out = (float*)d_out;

    cudaFuncSetAttribute(lstm_seq, cudaFuncAttributeMaxDynamicSharedMemorySize, SMEM_BYTES);

    xpre_mma<<<dim3(16, 256), 256>>>(x, Wx, bias);
    lstm_seq<<<NCTA, 256, SMEM_BYTES>>>(h0, c0, Wh, out);
}

// round 4
// speedup vs baseline: 1.8549x; 1.5566x over previous
#include <cuda_runtime.h>
#include <cuda_bf16.h>
#include <cstdint>
#include <cstddef>

// Problem constants
#define SEQ    512
#define BATCH  64
#define UNITS  512
#define GATES  2048          // 4*UNITS, Keras order i,f,g,o
#define NCTA   128           // persistent grid (<=148 SMs -> co-resident)

// -------------------- device scratch (no cudaMalloc allowed) --------------------
__device__ float g_xpre[(size_t)BATCH * SEQ * GATES];   // [b*512+t][gate_col], 256 MB
__device__ float g_h[2][BATCH * UNITS];                 // h [b][u], double buffered
__device__ unsigned g_arrive;                           // zero-initialized, monotonic
__device__ unsigned g_release;

// -------------------- helpers --------------------
__device__ __forceinline__ uint32_t f32_to_tf32(float x) {
    uint32_t r; asm("cvt.rna.tf32.f32 %0, %1;" : "=r"(r) : "f"(x)); return r;
}

__device__ __forceinline__ void mma_tf32(float c[4],
                                         uint32_t a0, uint32_t a1, uint32_t a2, uint32_t a3,
                                         uint32_t b0, uint32_t b1) {
    asm volatile(
        "mma.sync.aligned.m16n8k8.row.col.f32.tf32.tf32.f32 "
        "{%0,%1,%2,%3}, {%4,%5,%6,%7}, {%8,%9}, {%0,%1,%2,%3};"
        : "+f"(c[0]), "+f"(c[1]), "+f"(c[2]), "+f"(c[3])
        : "r"(a0), "r"(a1), "r"(a2), "r"(a3), "r"(b0), "r"(b1));
}

__device__ __forceinline__ void mma_bf16(float c[4],
                                         uint32_t a0, uint32_t a1, uint32_t a2, uint32_t a3,
                                         uint32_t b0, uint32_t b1) {
    asm volatile(
        "mma.sync.aligned.m16n8k16.row.col.f32.bf16.bf16.f32 "
        "{%0,%1,%2,%3}, {%4,%5,%6,%7}, {%8,%9}, {%0,%1,%2,%3};"
        : "+f"(c[0]), "+f"(c[1]), "+f"(c[2]), "+f"(c[3])
        : "r"(a0), "r"(a1), "r"(a2), "r"(a3), "r"(b0), "r"(b1));
}

__device__ __forceinline__ uint32_t packbf(__nv_bfloat16 lo, __nv_bfloat16 hi) {
    __nv_bfloat162 p = __halves2bfloat162(lo, hi);   // .x = lo 16 bits (even k)
    return *(uint32_t*)&p;
}

__device__ __forceinline__ float sigmoid_f(float x) {
    return 1.0f / (1.0f + __expf(-x));
}
__device__ __forceinline__ float tanh_f(float x) {
    float e = __expf(-2.0f * fabsf(x));
    float t = (1.0f - e) / (1.0f + e);
    return copysignf(t, x);
}

// Monotonic sense-free grid barrier (survives graph replays without reset).
__device__ __forceinline__ void grid_barrier() {
    __syncthreads();
    if (threadIdx.x == 0) {
        __threadfence();
        unsigned ticket = atomicAdd(&g_arrive, 1u);
        unsigned round  = ticket >> 7;                    // / NCTA (=128)
        if ((ticket & (NCTA - 1u)) == (NCTA - 1u)) {
            atomicAdd(&g_release, 1u);
        } else {
            while ((int)(*(volatile unsigned*)&g_release - (round + 1u)) < 0) { }
        }
        __threadfence();
    }
    __syncthreads();
}

// -------------------- kernel 1: Xpre = x @ Wx + bias (mma.sync tf32) --------------------
#define A_PITCH 36
#define B_PITCH 136

__global__ __launch_bounds__(256, 2) void xpre_mma(
    const float* __restrict__ X,     // [32768, 512]
    const float* __restrict__ Wx,    // [512, 2048]
    const float* __restrict__ bias)  // [2048]
{
    __shared__ uint32_t sA[128 * A_PITCH];   // 18 KB
    __shared__ uint32_t sB[32 * B_PITCH];    // 17.4 KB

    const int tid  = threadIdx.x;
    const int lane = tid & 31;
    const int wid  = tid >> 5;
    const int m0 = blockIdx.y << 7;
    const int n0 = blockIdx.x << 7;
    const int wr = wid >> 1;          // warp row 0..3 (32 rows each)
    const int wc = wid & 1;           // warp col 0..1 (64 cols each)
    const int gid = lane >> 2;        // 0..7
    const int tig = lane & 3;         // 0..3

    float acc[2][8][4];
#pragma unroll
    for (int mf = 0; mf < 2; mf++)
#pragma unroll
        for (int nf = 0; nf < 8; nf++)
#pragma unroll
            for (int q = 0; q < 4; q++) acc[mf][nf][q] = 0.0f;

    for (int kc = 0; kc < 16; kc++) {
        const int k0 = kc << 5;

#pragma unroll
        for (int it = 0; it < 4; it++) {
            int idx = tid + (it << 8);
            int row = idx >> 3;
            int c4  = (idx & 7) << 2;
            float4 v = *(const float4*)(X + (size_t)(m0 + row) * 512 + k0 + c4);
            uint4 t;
            t.x = f32_to_tf32(v.x); t.y = f32_to_tf32(v.y);
            t.z = f32_to_tf32(v.z); t.w = f32_to_tf32(v.w);
            *(uint4*)&sA[row * A_PITCH + c4] = t;
        }
#pragma unroll
        for (int it = 0; it < 4; it++) {
            int idx = tid + (it << 8);
            int k  = idx >> 5;
            int c4 = (idx & 31) << 2;
            float4 v = *(const float4*)(Wx + (size_t)(k0 + k) * 2048 + n0 + c4);
            uint4 t;
            t.x = f32_to_tf32(v.x); t.y = f32_to_tf32(v.y);
            t.z = f32_to_tf32(v.z); t.w = f32_to_tf32(v.w);
            *(uint4*)&sB[k * B_PITCH + c4] = t;
        }
        __syncthreads();

#pragma unroll
        for (int k8 = 0; k8 < 4; k8++) {
            const int kb = k8 << 3;
            uint32_t a[2][4];
#pragma unroll
            for (int mf = 0; mf < 2; mf++) {
                int r = wr * 32 + mf * 16 + gid;
                a[mf][0] = sA[r * A_PITCH + kb + tig];
                a[mf][1] = sA[(r + 8) * A_PITCH + kb + tig];
                a[mf][2] = sA[r * A_PITCH + kb + tig + 4];
                a[mf][3] = sA[(r + 8) * A_PITCH + kb + tig + 4];
            }
#pragma unroll
            for (int nf = 0; nf < 8; nf++) {
                int n = wc * 64 + nf * 8 + gid;
                uint32_t b0 = sB[(kb + tig) * B_PITCH + n];
                uint32_t b1 = sB[(kb + tig + 4) * B_PITCH + n];
                mma_tf32(acc[0][nf], a[0][0], a[0][1], a[0][2], a[0][3], b0, b1);
                mma_tf32(acc[1][nf], a[1][0], a[1][1], a[1][2], a[1][3], b0, b1);
            }
        }
        __syncthreads();
    }

#pragma unroll
    for (int nf = 0; nf < 8; nf++) {
        int col = n0 + wc * 64 + nf * 8 + tig * 2;
        float bv0 = bias[col], bv1 = bias[col + 1];
#pragma unroll
        for (int mf = 0; mf < 2; mf++) {
            int r0 = m0 + wr * 32 + mf * 16 + gid;
            float2 lo = make_float2(acc[mf][nf][0] + bv0, acc[mf][nf][1] + bv1);
            float2 hi = make_float2(acc[mf][nf][2] + bv0, acc[mf][nf][3] + bv1);
            *(float2*)&g_xpre[(size_t)r0 * 2048 + col]       = lo;
            *(float2*)&g_xpre[(size_t)(r0 + 8) * 2048 + col] = hi;
        }
    }
}

// -------------------- kernel 2: persistent LSTM recurrence (bf16x3 mma) --------------------
// 128 CTAs = 4 batch-groups (16 batches) x 32 unit-groups (16 units).
// Per step per CTA: Z[16b x 64c] (c = gate*16+j) = Xpre + H[16x512] @ WhSlice[512x64].
// Wh slice pre-split (hi,lo bf16) into smem as uint2 words packing 2 k's; H
// re-split each step. 8 warps: warp (gate, jhalf) owns 8 unit-cols, full K in
// register accumulators (3 independent sets for the 3 split products).
//
// smem (uint2 units): sW[256*68] | sH[16*260] | sZ (1024 floats)
#define WP 68
#define HP 260
#define SW_U2 (256 * WP)             // 17408
#define SH_U2 (16 * HP)              // 4160
#define SMEM_BYTES ((SW_U2 + SH_U2) * 8 + 1024 * 4)

__global__ __launch_bounds__(256, 1) void lstm_seq2(
    const float* __restrict__ h0g,  // [64, 512]
    const float* __restrict__ c0,   // [64, 512]
    const float* __restrict__ Wh,   // [512, 2048]
    float* __restrict__ out)        // [512, 64, 512]
{
    extern __shared__ uint2 sm2[];
    uint2* sW = sm2;                  // [kp][c] kp=0..255 (pairs of k), c=0..63(+pad)
    uint2* sH = sm2 + SW_U2;          // [row b][kp]  (x=hi pack, y=lo pack)
    float* sZ = (float*)(sm2 + SW_U2 + SH_U2);   // [gate][16b][16u]

    const int tid  = threadIdx.x;
    const int lane = tid & 31;
    const int wid  = tid >> 5;
    const int cg = blockIdx.x & 31;      // unit group
    const int bg = blockIdx.x >> 5;      // batch group
    const int u0 = cg << 4;
    const int b0 = bg << 4;

    // ---- one-time: split Wh slice into smem (hi,lo) packed words
    for (int idx = tid; idx < 16384; idx += 256) {
        int kp = idx >> 6;               // 0..255
        int c  = idx & 63;               // gate*16 + j
        int gate = c >> 4, j = c & 15;
        int col = gate * 512 + u0 + j;
        float w0 = Wh[(size_t)(2 * kp) * 2048 + col];
        float w1 = Wh[(size_t)(2 * kp + 1) * 2048 + col];
        __nv_bfloat16 h0b = __float2bfloat16_rn(w0);
        __nv_bfloat16 h1b = __float2bfloat16_rn(w1);
        __nv_bfloat16 l0b = __float2bfloat16_rn(w0 - __bfloat162float(h0b));
        __nv_bfloat16 l1b = __float2bfloat16_rn(w1 - __bfloat162float(h1b));
        sW[kp * WP + c] = make_uint2(packbf(h0b, h1b), packbf(l0b, l1b));
    }

    // ---- per-thread cell state (b = tid>>4, u = tid&15)
    const int bl = tid >> 4, ul = tid & 15;
    float c_reg = c0[(size_t)(b0 + bl) * 512 + u0 + ul];

    // ---- warp roles for mma
    const int gate_w = wid >> 1;         // 0..3
    const int jh = wid & 1;              // unit half (8 cols)
    const int g = lane >> 2;             // 0..7
    const int t4 = lane & 3;             // 0..3
    const int n0c = gate_w * 16 + jh * 8;

    const uint2* hA  = sH + g * HP;
    const uint2* hA8 = sH + (g + 8) * HP;
    const uint2* bW  = sW + n0c + g;

    for (int tstep = 0; tstep < SEQ; tstep++) {
        const float* hsrc = (tstep == 0) ? h0g : g_h[tstep & 1];

        // ---- H load + bf16 split into sH (16 rows x 512 u)
        {
            const float4* hs4 = (const float4*)(hsrc + (size_t)b0 * 512);
#pragma unroll
            for (int it = 0; it < 8; it++) {
                int i = tid + (it << 8);         // 0..2047 float4s
                int row = i >> 7, u4 = i & 127;
                float4 v = hs4[row * 128 + u4];
                __nv_bfloat16 bx = __float2bfloat16_rn(v.x);
                __nv_bfloat16 by = __float2bfloat16_rn(v.y);
                __nv_bfloat16 bz = __float2bfloat16_rn(v.z);
                __nv_bfloat16 bw = __float2bfloat16_rn(v.w);
                __nv_bfloat16 rx = __float2bfloat16_rn(v.x - __bfloat162float(bx));
                __nv_bfloat16 ry = __float2bfloat16_rn(v.y - __bfloat162float(by));
                __nv_bfloat16 rz = __float2bfloat16_rn(v.z - __bfloat162float(bz));
                __nv_bfloat16 rw = __float2bfloat16_rn(v.w - __bfloat162float(bw));
                sH[row * HP + u4 * 2]     = make_uint2(packbf(bx, by), packbf(rx, ry));
                sH[row * HP + u4 * 2 + 1] = make_uint2(packbf(bz, bw), packbf(rz, rw));
            }
        }

        // ---- prefill sZ with Xpre tile (coalesced)
#pragma unroll
        for (int m = 0; m < 4; m++) {
            int o = tid + (m << 8);
            int bb = o >> 6, cc = o & 63;
            int gate = cc >> 4, j = cc & 15;
            sZ[gate * 256 + bb * 16 + j] =
                g_xpre[((size_t)(b0 + bb) * 512 + tstep) * 2048 + gate * 512 + u0 + j];
        }
        __syncthreads();

        // ---- GEMM: 3-product bf16 split, full K in registers
        float accA[4] = {0.f, 0.f, 0.f, 0.f};
        float accB[4] = {0.f, 0.f, 0.f, 0.f};
        float accC[4] = {0.f, 0.f, 0.f, 0.f};
#pragma unroll 4
        for (int kb = 0; kb < 32; kb++) {
            int wa = kb * 8 + t4;
            uint2 a0 = hA[wa];
            uint2 a1 = hA8[wa];
            uint2 a2 = hA[wa + 4];
            uint2 a3 = hA8[wa + 4];
            uint2 b0 = bW[wa * WP];
            uint2 b1 = bW[(wa + 4) * WP];
            mma_bf16(accA, a0.x, a1.x, a2.x, a3.x, b0.x, b1.x);   // h_hi @ W_hi
            mma_bf16(accB, a0.x, a1.x, a2.x, a3.x, b0.y, b1.y);   // h_hi @ W_lo
            mma_bf16(accC, a0.y, a1.y, a2.y, a3.y, b0.x, b1.x);   // h_lo @ W_hi
        }

        // ---- add fragments into sZ (each element owned by exactly one thread)
        {
            int u = jh * 8 + 2 * t4;
            int i0 = gate_w * 256 + g * 16 + u;
            int i1 = gate_w * 256 + (g + 8) * 16 + u;
            sZ[i0]     += accA[0] + accB[0] + accC[0];
            sZ[i0 + 1] += accA[1] + accB[1] + accC[1];
            sZ[i1]     += accA[2] + accB[2] + accC[2];
            sZ[i1 + 1] += accA[3] + accB[3] + accC[3];
        }
        __syncthreads();

        // ---- elementwise LSTM cell (Keras gate order i,f,g,o)
        {
            float zi = sZ[tid];
            float zf = sZ[256 + tid];
            float zg = sZ[512 + tid];
            float zo = sZ[768 + tid];
            float ig = sigmoid_f(zi);
            float fg = sigmoid_f(zf);
            float gg = tanh_f(zg);
            float og = sigmoid_f(zo);
            c_reg = fg * c_reg + ig * gg;
            float hv = og * tanh_f(c_reg);
            g_h[(tstep & 1) ^ 1][(size_t)(b0 + bl) * 512 + u0 + ul] = hv;
            out[((size_t)tstep * 64 + b0 + bl) * 512 + u0 + ul] = hv;
        }

        grid_barrier();    // h fully published before next step reads it
    }
}

// -------------------- launch --------------------
// Input order (metadata): x [64,512,512], h0 [64,512], c0 [64,512],
//                         Wx [512,2048], Wh [512,2048], b [2048]
extern "C" void kernel_launch(void* const* d_in, const int* in_sizes, int n_in,
                              void* d_out, int out_size) {
    const float* x    = (const float*)d_in[0];
    const float* h0   = (const float*)d_in[1];
    const float* c0   = (const float*)d_in[2];
    const float* Wx   = (const float*)d_in[3];
    const float* Wh   = (const float*)d_in[4];
    const float* bias = (const float*)d_in[5];
    float* out = (float*)d_out;

    cudaFuncSetAttribute(lstm_seq2, cudaFuncAttributeMaxDynamicSharedMemorySize, SMEM_BYTES);

    xpre_mma<<<dim3(16, 256), 256>>>(x, Wx, bias);
    lstm_seq2<<<NCTA, 256, SMEM_BYTES>>>(h0, c0, Wh, out);
}

// round 5
// speedup vs baseline: 2.2189x; 1.1962x over previous
#include <cuda_runtime.h>
#include <cuda_bf16.h>
#include <cstdint>
#include <cstddef>

// Problem constants
#define SEQ    512
#define BATCH  64
#define UNITS  512
#define GATES  2048          // 4*UNITS, Keras order i,f,g,o
#define NCTA   128           // persistent grid (<=148 SMs -> co-resident)

// -------------------- device scratch (no cudaMalloc allowed) --------------------
__device__ float g_xpre[(size_t)SEQ * BATCH * GATES];        // [t][b][gate_col]
__device__ __nv_bfloat16 g_hh[2][BATCH * UNITS];             // h hi, double buffered
__device__ __nv_bfloat16 g_hl[2][BATCH * UNITS];             // h lo
__device__ unsigned g_barr_arrive[4][32];                    // per-bg, padded
__device__ unsigned g_barr_release[4][32];

// -------------------- helpers --------------------
__device__ __forceinline__ uint32_t f32_to_tf32(float x) {
    uint32_t r; asm("cvt.rna.tf32.f32 %0, %1;" : "=r"(r) : "f"(x)); return r;
}

__device__ __forceinline__ void mma_tf32(float c[4],
                                         uint32_t a0, uint32_t a1, uint32_t a2, uint32_t a3,
                                         uint32_t b0, uint32_t b1) {
    asm volatile(
        "mma.sync.aligned.m16n8k8.row.col.f32.tf32.tf32.f32 "
        "{%0,%1,%2,%3}, {%4,%5,%6,%7}, {%8,%9}, {%0,%1,%2,%3};"
        : "+f"(c[0]), "+f"(c[1]), "+f"(c[2]), "+f"(c[3])
        : "r"(a0), "r"(a1), "r"(a2), "r"(a3), "r"(b0), "r"(b1));
}

__device__ __forceinline__ void mma_bf16(float c[4],
                                         uint32_t a0, uint32_t a1, uint32_t a2, uint32_t a3,
                                         uint32_t b0, uint32_t b1) {
    asm volatile(
        "mma.sync.aligned.m16n8k16.row.col.f32.bf16.bf16.f32 "
        "{%0,%1,%2,%3}, {%4,%5,%6,%7}, {%8,%9}, {%0,%1,%2,%3};"
        : "+f"(c[0]), "+f"(c[1]), "+f"(c[2]), "+f"(c[3])
        : "r"(a0), "r"(a1), "r"(a2), "r"(a3), "r"(b0), "r"(b1));
}

__device__ __forceinline__ uint32_t packbf(__nv_bfloat16 lo, __nv_bfloat16 hi) {
    __nv_bfloat162 p = __halves2bfloat162(lo, hi);   // .x = low 16 bits (even k)
    return *(uint32_t*)&p;
}

__device__ __forceinline__ float sigmoid_f(float x) {
    return 1.0f / (1.0f + __expf(-x));
}
__device__ __forceinline__ float tanh_f(float x) {
    float e = __expf(-2.0f * fabsf(x));
    float t = (1.0f - e) / (1.0f + e);
    return copysignf(t, x);
}

// Per-batch-group monotonic barrier over 32 CTAs (graph-replay safe).
__device__ __forceinline__ void bg_barrier(int bg) {
    __syncthreads();
    if (threadIdx.x == 0) {
        __threadfence();
        unsigned ticket = atomicAdd(&g_barr_arrive[bg][0], 1u);
        unsigned round  = ticket >> 5;                    // / 32 CTAs
        if ((ticket & 31u) == 31u) {
            atomicAdd(&g_barr_release[bg][0], 1u);
        } else {
            while ((int)(*(volatile unsigned*)&g_barr_release[bg][0] - (round + 1u)) < 0) { }
        }
        __threadfence();
    }
    __syncthreads();
}

// -------------------- kernel 1: Xpre = x @ Wx + bias (mma.sync tf32) --------------------
// Output layout: time-major g_xpre[t][b][col].
#define A_PITCH 36
#define B_PITCH 136

__global__ __launch_bounds__(256, 2) void xpre_mma(
    const float* __restrict__ X,     // [32768, 512] rows m = b*512 + t
    const float* __restrict__ Wx,    // [512, 2048]
    const float* __restrict__ bias)  // [2048]
{
    __shared__ uint32_t sA[128 * A_PITCH];   // 18 KB
    __shared__ uint32_t sB[32 * B_PITCH];    // 17.4 KB

    const int tid  = threadIdx.x;
    const int lane = tid & 31;
    const int wid  = tid >> 5;
    const int m0 = blockIdx.y << 7;
    const int n0 = blockIdx.x << 7;
    const int wr = wid >> 1;
    const int wc = wid & 1;
    const int gid = lane >> 2;
    const int tig = lane & 3;

    float acc[2][8][4];
#pragma unroll
    for (int mf = 0; mf < 2; mf++)
#pragma unroll
        for (int nf = 0; nf < 8; nf++)
#pragma unroll
            for (int q = 0; q < 4; q++) acc[mf][nf][q] = 0.0f;

    for (int kc = 0; kc < 16; kc++) {
        const int k0 = kc << 5;

#pragma unroll
        for (int it = 0; it < 4; it++) {
            int idx = tid + (it << 8);
            int row = idx >> 3;
            int c4  = (idx & 7) << 2;
            float4 v = *(const float4*)(X + (size_t)(m0 + row) * 512 + k0 + c4);
            uint4 t;
            t.x = f32_to_tf32(v.x); t.y = f32_to_tf32(v.y);
            t.z = f32_to_tf32(v.z); t.w = f32_to_tf32(v.w);
            *(uint4*)&sA[row * A_PITCH + c4] = t;
        }
#pragma unroll
        for (int it = 0; it < 4; it++) {
            int idx = tid + (it << 8);
            int k  = idx >> 5;
            int c4 = (idx & 31) << 2;
            float4 v = *(const float4*)(Wx + (size_t)(k0 + k) * 2048 + n0 + c4);
            uint4 t;
            t.x = f32_to_tf32(v.x); t.y = f32_to_tf32(v.y);
            t.z = f32_to_tf32(v.z); t.w = f32_to_tf32(v.w);
            *(uint4*)&sB[k * B_PITCH + c4] = t;
        }
        __syncthreads();

#pragma unroll
        for (int k8 = 0; k8 < 4; k8++) {
            const int kb = k8 << 3;
            uint32_t a[2][4];
#pragma unroll
            for (int mf = 0; mf < 2; mf++) {
                int r = wr * 32 + mf * 16 + gid;
                a[mf][0] = sA[r * A_PITCH + kb + tig];
                a[mf][1] = sA[(r + 8) * A_PITCH + kb + tig];
                a[mf][2] = sA[r * A_PITCH + kb + tig + 4];
                a[mf][3] = sA[(r + 8) * A_PITCH + kb + tig + 4];
            }
#pragma unroll
            for (int nf = 0; nf < 8; nf++) {
                int n = wc * 64 + nf * 8 + gid;
                uint32_t b0 = sB[(kb + tig) * B_PITCH + n];
                uint32_t b1 = sB[(kb + tig + 4) * B_PITCH + n];
                mma_tf32(acc[0][nf], a[0][0], a[0][1], a[0][2], a[0][3], b0, b1);
                mma_tf32(acc[1][nf], a[1][0], a[1][1], a[1][2], a[1][3], b0, b1);
            }
        }
        __syncthreads();
    }

    // epilogue -> time-major [t][b][col]
    const int bidx = m0 >> 9;   // batch constant within this 128-row tile
#pragma unroll
    for (int nf = 0; nf < 8; nf++) {
        int col = n0 + wc * 64 + nf * 8 + tig * 2;
        float bv0 = bias[col], bv1 = bias[col + 1];
#pragma unroll
        for (int mf = 0; mf < 2; mf++) {
            int r0 = m0 + wr * 32 + mf * 16 + gid;
            int t0 = r0 & 511;
            float2 lo = make_float2(acc[mf][nf][0] + bv0, acc[mf][nf][1] + bv1);
            float2 hi = make_float2(acc[mf][nf][2] + bv0, acc[mf][nf][3] + bv1);
            *(float2*)&g_xpre[((size_t)t0 * 64 + bidx) * 2048 + col]       = lo;
            *(float2*)&g_xpre[((size_t)(t0 + 8) * 64 + bidx) * 2048 + col] = hi;
        }
    }
}

// -------------------- kernel 2: persistent LSTM recurrence --------------------
// 128 CTAs = 4 bg (16 batches) x 32 ug (16 units). Per step per CTA:
// Z[16b x 64c] = Xpre + H[16x512] @ Wh_slice[512x64], bf16 3-term split.
// 4 GEMM warps (warp = gate, n=16 = two m16n8 halves, full K in regs);
// warps 4-7 load Xpre into sZ concurrently. h stored pre-split in global.
#define WP  68            // sW pitch (uint2)
#define HPP 260           // sHh/sHl pitch (uint32)
#define SW_BYTES (256 * WP * 8)
#define SH_BYTES (16 * HPP * 4)
#define SMEM_BYTES (SW_BYTES + 2 * SH_BYTES + 1024 * 4)

__global__ __launch_bounds__(256, 1) void lstm_seq3(
    const float* __restrict__ h0g,  // [64, 512]
    const float* __restrict__ c0,   // [64, 512]
    const float* __restrict__ Wh,   // [512, 2048]
    float* __restrict__ out)        // [512, 64, 512]
{
    extern __shared__ char smraw[];
    uint2*    sW  = (uint2*)smraw;                       // [kp 256][c 64] (+pad)
    uint32_t* sHh = (uint32_t*)(smraw + SW_BYTES);       // [row 16][kp 256] (+pad)
    uint32_t* sHl = sHh + 16 * HPP;
    float*    sZ  = (float*)(smraw + SW_BYTES + 2 * SH_BYTES);  // [gate][16b][16u]

    const int tid  = threadIdx.x;
    const int lane = tid & 31;
    const int wid  = tid >> 5;
    const int cg = blockIdx.x & 31;      // unit group
    const int bg = blockIdx.x >> 5;      // batch group
    const int u0 = cg << 4;
    const int b0 = bg << 4;

    // ---- one-time: split Wh slice into smem (hi,lo) packed words
    for (int idx = tid; idx < 16384; idx += 256) {
        int kp = idx >> 6;               // 0..255 (pairs of k)
        int c  = idx & 63;               // gate*16 + j
        int gate = c >> 4, j = c & 15;
        int col = gate * 512 + u0 + j;
        float w0 = Wh[(size_t)(2 * kp) * 2048 + col];
        float w1 = Wh[(size_t)(2 * kp + 1) * 2048 + col];
        __nv_bfloat16 h0b = __float2bfloat16_rn(w0);
        __nv_bfloat16 h1b = __float2bfloat16_rn(w1);
        __nv_bfloat16 l0b = __float2bfloat16_rn(w0 - __bfloat162float(h0b));
        __nv_bfloat16 l1b = __float2bfloat16_rn(w1 - __bfloat162float(h1b));
        sW[kp * WP + c] = make_uint2(packbf(h0b, h1b), packbf(l0b, l1b));
    }

    // ---- per-thread cell state + initial h split (own (b,u) element)
    const int bl = tid >> 4, ul = tid & 15;
    const int gidx = (b0 + bl) * 512 + u0 + ul;
    float c_reg = c0[gidx];
    {
        float hv0 = h0g[gidx];
        __nv_bfloat16 hi = __float2bfloat16_rn(hv0);
        __nv_bfloat16 lo = __float2bfloat16_rn(hv0 - __bfloat162float(hi));
        g_hh[0][gidx] = hi;
        g_hl[0][gidx] = lo;
    }

    // ---- GEMM warp constants (wid 0..3, warp = gate)
    const int g  = lane >> 2;            // 0..7
    const int t4 = lane & 3;             // 0..3
    const uint32_t* Ah  = sHh + g * HPP;
    const uint32_t* Ah8 = sHh + (g + 8) * HPP;
    const uint32_t* Al  = sHl + g * HPP;
    const uint32_t* Al8 = sHl + (g + 8) * HPP;
    const uint2* Bw0 = sW + (wid * 16 + g);        // half 0 cols
    const uint2* Bw1 = sW + (wid * 16 + 8 + g);    // half 1 cols

    bg_barrier(bg);                      // h0 split visible within batch group

    for (int tstep = 0; tstep < SEQ; tstep++) {
        const int rb = tstep & 1;

        // ---- copy pre-split H tile into smem (pure uint4 copy)
        {
            const uint4* srcHh = (const uint4*)(g_hh[rb] + (size_t)b0 * 512);
            const uint4* srcHl = (const uint4*)(g_hl[rb] + (size_t)b0 * 512);
#pragma unroll
            for (int it = 0; it < 4; it++) {
                int i = tid + (it << 8);        // 0..1023
                int row = i >> 6, q = i & 63;   // q: group of 4 k-pairs
                *(uint4*)&sHh[row * HPP + q * 4] = srcHh[row * 64 + q];
                *(uint4*)&sHl[row * HPP + q * 4] = srcHl[row * 64 + q];
            }
        }
        __syncthreads();

        float a00[4] = {0,0,0,0}, a01[4] = {0,0,0,0}, a02[4] = {0,0,0,0};
        float a10[4] = {0,0,0,0}, a11[4] = {0,0,0,0}, a12[4] = {0,0,0,0};

        if (wid < 4) {
            // ---- GEMM: 3-product bf16 split, n=16 (two n8 halves), full K
#pragma unroll 4
            for (int kb = 0; kb < 32; kb++) {
                int wa = kb * 8 + t4;
                uint32_t ah0 = Ah[wa],  ah1 = Ah8[wa];
                uint32_t ah2 = Ah[wa + 4], ah3 = Ah8[wa + 4];
                uint32_t al0 = Al[wa],  al1 = Al8[wa];
                uint32_t al2 = Al[wa + 4], al3 = Al8[wa + 4];
                uint2 b00 = Bw0[wa * WP], b01 = Bw0[(wa + 4) * WP];
                uint2 b10 = Bw1[wa * WP], b11 = Bw1[(wa + 4) * WP];
                mma_bf16(a00, ah0, ah1, ah2, ah3, b00.x, b01.x);  // h_hi @ W_hi
                mma_bf16(a01, ah0, ah1, ah2, ah3, b00.y, b01.y);  // h_hi @ W_lo
                mma_bf16(a02, al0, al1, al2, al3, b00.x, b01.x);  // h_lo @ W_hi
                mma_bf16(a10, ah0, ah1, ah2, ah3, b10.x, b11.x);
                mma_bf16(a11, ah0, ah1, ah2, ah3, b10.y, b11.y);
                mma_bf16(a12, al0, al1, al2, al3, b10.x, b11.x);
            }
        } else {
            // ---- warps 4-7: Xpre tile -> sZ (overlapped with GEMM)
            int tl = tid - 128;
            const float* xsrc = g_xpre + ((size_t)tstep * 64 + b0) * 2048 + u0;
#pragma unroll
            for (int it = 0; it < 8; it++) {
                int o = tl + (it << 7);          // 0..1023 = gate*256 + bb*16 + j
                int gate = o >> 8, bb = (o >> 4) & 15, j = o & 15;
                sZ[o] = xsrc[(size_t)bb * 2048 + gate * 512 + j];
            }
        }
        __syncthreads();

        // ---- GEMM warps fold accumulators into sZ
        if (wid < 4) {
            int base0 = wid * 256 + 2 * t4;
            sZ[base0 + g * 16]           += a00[0] + a01[0] + a02[0];
            sZ[base0 + g * 16 + 1]       += a00[1] + a01[1] + a02[1];
            sZ[base0 + (g + 8) * 16]     += a00[2] + a01[2] + a02[2];
            sZ[base0 + (g + 8) * 16 + 1] += a00[3] + a01[3] + a02[3];
            int base1 = base0 + 8;
            sZ[base1 + g * 16]           += a10[0] + a11[0] + a12[0];
            sZ[base1 + g * 16 + 1]       += a10[1] + a11[1] + a12[1];
            sZ[base1 + (g + 8) * 16]     += a10[2] + a11[2] + a12[2];
            sZ[base1 + (g + 8) * 16 + 1] += a10[3] + a11[3] + a12[3];
        }
        __syncthreads();

        // ---- elementwise LSTM cell (Keras gate order i,f,g,o)
        float hv;
        {
            float zi = sZ[tid];
            float zf = sZ[256 + tid];
            float zg = sZ[512 + tid];
            float zo = sZ[768 + tid];
            float ig = sigmoid_f(zi);
            float fg = sigmoid_f(zf);
            float gg = tanh_f(zg);
            float og = sigmoid_f(zo);
            c_reg = fg * c_reg + ig * gg;
            hv = og * tanh_f(c_reg);
            __nv_bfloat16 hi = __float2bfloat16_rn(hv);
            __nv_bfloat16 lo = __float2bfloat16_rn(hv - __bfloat162float(hi));
            g_hh[rb ^ 1][gidx] = hi;
            g_hl[rb ^ 1][gidx] = lo;
        }

        bg_barrier(bg);    // h(t+1) published within batch group

        // out store off the critical path (after the barrier)
        out[((size_t)tstep * 64 + b0 + bl) * 512 + u0 + ul] = hv;
    }
}

// -------------------- launch --------------------
// Input order (metadata): x [64,512,512], h0 [64,512], c0 [64,512],
//                         Wx [512,2048], Wh [512,2048], b [2048]
extern "C" void kernel_launch(void* const* d_in, const int* in_sizes, int n_in,
                              void* d_out, int out_size) {
    const float* x    = (const float*)d_in[0];
    const float* h0   = (const float*)d_in[1];
    const float* c0   = (const float*)d_in[2];
    const float* Wx   = (const float*)d_in[3];
    const float* Wh   = (const float*)d_in[4];
    const float* bias = (const float*)d_in[5];
    float* out = (float*)d_out;

    cudaFuncSetAttribute(lstm_seq3, cudaFuncAttributeMaxDynamicSharedMemorySize, SMEM_BYTES);

    xpre_mma<<<dim3(16, 256), 256>>>(x, Wx, bias);
    lstm_seq3<<<NCTA, 256, SMEM_BYTES>>>(h0, c0, Wh, out);
}